// round 17
// baseline (speedup 1.0000x reference)
#include <cuda_runtime.h>
#include <cuda_fp16.h>
#include <cstdint>

#define BB   4
#define SQL  4096
#define SKVL 4096
#define DINL 256
#define DKL  256

// fp16 projected tensors. V stored TRANSPOSED: [b][d][skv]
__device__ __align__(16) __half g_Qh[(size_t)BB * SQL  * DKL];
__device__ __align__(16) __half g_Kh[(size_t)BB * SKVL * DKL];
__device__ __align__(16) __half g_Vt[(size_t)BB * DKL * SKVL];
// fp16 copies of the conv inputs
__device__ __align__(16) __half g_AL[(size_t)BB * SKVL * DINL];
__device__ __align__(16) __half g_AG[(size_t)BB * SQL  * DINL];
// transposed fp16 weights: [n][k]   (0=K, 1=V, 2=Q)
__device__ __align__(16) __half g_Wt[3][DINL * DKL];

// ---------------- PTX helpers ----------------
__device__ __forceinline__ uint32_t smem_u32(const void* p) {
    uint32_t a;
    asm("{ .reg .u64 t; cvta.to.shared.u64 t, %1; cvt.u32.u64 %0, t; }" : "=r"(a) : "l"(p));
    return a;
}
__device__ __forceinline__ void cp16(uint32_t dst, const void* src) {
    asm volatile("cp.async.cg.shared.global [%0], [%1], 16;\n" :: "r"(dst), "l"(src));
}
#define CP_COMMIT() asm volatile("cp.async.commit_group;\n" ::: "memory")
#define CP_WAIT1()  asm volatile("cp.async.wait_group 1;\n"  ::: "memory")
#define CP_WAIT0()  asm volatile("cp.async.wait_group 0;\n"  ::: "memory")

__device__ __forceinline__ void ldm4(uint32_t* r, uint32_t addr) {
    asm volatile("ldmatrix.sync.aligned.m8n8.x4.shared.b16 {%0,%1,%2,%3}, [%4];"
        : "=r"(r[0]), "=r"(r[1]), "=r"(r[2]), "=r"(r[3]) : "r"(addr));
}
__device__ __forceinline__ void mma16816(float* d, const uint32_t* a,
                                         uint32_t b0, uint32_t b1) {
    asm volatile("mma.sync.aligned.m16n8k16.row.col.f32.f16.f16.f32 "
        "{%0,%1,%2,%3}, {%4,%5,%6,%7}, {%8,%9}, {%0,%1,%2,%3};"
        : "+f"(d[0]), "+f"(d[1]), "+f"(d[2]), "+f"(d[3])
        : "r"(a[0]), "r"(a[1]), "r"(a[2]), "r"(a[3]), "r"(b0), "r"(b1));
}

// ---------------- attn smem map (bytes) ----------------
// Q   : [64 rows][264 h]                     33792
// ring: 3 slots x 18432.  K slot: [64 kv][136 h]=17408.  V slot: [128 d][72 h]=18432
// P   : [64 rows][72 h]                      9216
// Lb  : 4 banks x 64 floats                  1024
#define QO     0
#define RINGO  33792
#define SLOTB  18432
#define PO     89088
#define LO     98304
#define SMEM_ATTN 99328

// ---------------- attention kernel ----------------
// BM=64 q rows/CTA, BN=64 kv/tile, 256 threads (8 warps: wm x2, wn x4).
// 2 CTAs/SM -> cross-CTA overlap hides softmax/barrier dead time.
// 3 phases/tile: S-d0 | S-d1 + softmax | PV (both V chunks merged).
// Slot schedule (mod 3): K0@t, K1@t+1, V0@t+2, V1@t; waits 0 / 1 / 0.
__global__ __launch_bounds__(256, 2) void attn_kernel(float* __restrict__ out) {
    extern __shared__ char sm[];
    const uint32_t smb = smem_u32(sm);
    float* sLb = (float*)(sm + LO);

    const int tid = threadIdx.x;
    const int lane = tid & 31;
    const int w = tid >> 5;
    const int wm = w & 1;          // 2 row groups of 32
    const int wn = w >> 1;         // 4 groups: S 16 kv / PV 32 d
    const int b  = blockIdx.x >> 6;
    const int q0 = (blockIdx.x & 63) * 64;

    const __half* Qg = g_Qh + ((size_t)(b * SQL + q0)) * DKL;
    const __half* Kg = g_Kh + (size_t)b * SKVL * DKL;
    const __half* Vg = g_Vt + (size_t)b * DKL * SKVL;

    sLb[tid] = 0.f;

    const int lrow = lane & 15;
    const int lseg = (lane >> 4) * 8;
    const uint32_t aq_base = smb + QO + ((wm * 32 + lrow) * 264 + lseg) * 2;
    const uint32_t ap_base = smb + PO + ((wm * 32 + lrow) * 72 + lseg) * 2;
    const uint32_t kb_off  = ((wn * 16 + lrow) * 136 + lseg) * 2;   // K slot
    const uint32_t vb_off  = ((wn * 32 + lrow) * 72 + lseg) * 2;    // V slot

    float O[2][2][4][4];           // [vc][mt][nt2*2+j][reg]
#pragma unroll
    for (int v = 0; v < 2; v++)
#pragma unroll
        for (int m = 0; m < 2; m++)
#pragma unroll
            for (int n = 0; n < 4; n++)
#pragma unroll
                for (int q = 0; q < 4; q++) O[v][m][n][q] = 0.f;

    auto ld_k = [&](int slot, int t, int kc) {
#pragma unroll
        for (int r = 0; r < 4; r++) {
            int idx = tid + r * 256;
            int row = idx >> 4, seg = idx & 15;          // 64 kv rows x 16 segs
            cp16(smb + RINGO + slot * SLOTB + (row * 136 + seg * 8) * 2,
                 Kg + ((size_t)(t * 64 + row)) * DKL + kc * 128 + seg * 8);
        }
    };
    auto ld_v = [&](int slot, int t, int vc) {
#pragma unroll
        for (int r = 0; r < 4; r++) {
            int idx = tid + r * 256;
            int row = idx >> 3, seg = idx & 7;           // 128 d rows x 8 segs
            cp16(smb + RINGO + slot * SLOTB + (row * 72 + seg * 8) * 2,
                 Vg + ((size_t)(vc * 128 + row)) * SKVL + t * 64 + seg * 8);
        }
    };

    // prologue: Q + K0(0) -> slot0 (one group)
#pragma unroll
    for (int r = 0; r < 8; r++) {
        int idx = tid + r * 256;
        int row = idx >> 5, seg = idx & 31;              // 64 rows x 32 segs
        cp16(smb + QO + (row * 264 + seg * 8) * 2,
             Qg + (size_t)row * DKL + seg * 8);
    }
    ld_k(0, 0, 0);
    CP_COMMIT();

    float S[2][2][4];              // [mt][nt][reg]

    auto s_comp = [&](uint32_t ring, int kcb) {
        const uint32_t rb  = ring + kb_off;
        const uint32_t aq0 = aq_base + kcb * 2;
        const uint32_t aq1 = aq0 + 16 * 264 * 2;
#pragma unroll
        for (int ks = 0; ks < 8; ks++) {
            const int kb = ks * 32;                      // bytes (16 halfs)
            uint32_t a[2][4], bb[4];
            ldm4(a[0], aq0 + kb);
            ldm4(a[1], aq1 + kb);
            ldm4(bb, rb + kb);
#pragma unroll
            for (int mt = 0; mt < 2; mt++) {
                mma16816(S[mt][0], a[mt], bb[0], bb[2]);
                mma16816(S[mt][1], a[mt], bb[1], bb[3]);
            }
        }
    };
    // merged PV: both V chunks (ring0 -> O[0], ring1 -> O[1])
    auto pv2 = [&](uint32_t ring0, uint32_t ring1) {
        const uint32_t r0a = ring0 + vb_off, r0b = r0a + 16 * 72 * 2;
        const uint32_t r1a = ring1 + vb_off, r1b = r1a + 16 * 72 * 2;
        const uint32_t ap1 = ap_base + 16 * 72 * 2;
#pragma unroll
        for (int ks = 0; ks < 4; ks++) {
            const int kb = ks * 32;
            uint32_t a[2][4], b0[2][4], b1[2][4];
            ldm4(a[0], ap_base + kb);
            ldm4(a[1], ap1 + kb);
            ldm4(b0[0], r0a + kb);
            ldm4(b0[1], r0b + kb);
            ldm4(b1[0], r1a + kb);
            ldm4(b1[1], r1b + kb);
#pragma unroll
            for (int mt = 0; mt < 2; mt++)
#pragma unroll
                for (int nt2 = 0; nt2 < 2; nt2++) {
                    mma16816(O[0][mt][nt2 * 2 + 0], a[mt], b0[nt2][0], b0[nt2][2]);
                    mma16816(O[0][mt][nt2 * 2 + 1], a[mt], b0[nt2][1], b0[nt2][3]);
                    mma16816(O[1][mt][nt2 * 2 + 0], a[mt], b1[nt2][0], b1[nt2][2]);
                    mma16816(O[1][mt][nt2 * 2 + 1], a[mt], b1[nt2][1], b1[nt2][3]);
                }
        }
    };

    const int NT = SKVL / 64;
    int t3 = 0;

    for (int t = 0; t < NT; t++) {
        const int s0 = t3;                               // K0 / V1
        const int s1 = (t3 + 1 == 3) ? 0 : t3 + 1;       // K1 ; next K0
        const int s2 = (t3 + 2 >= 3) ? t3 - 1 : t3 + 2;  // V0

        // ===== phase 0: S over d[0:128) from s0 =====
        CP_WAIT0();
        __syncthreads();
        ld_k(s1, t, 1); CP_COMMIT();
        ld_v(s2, t, 0); CP_COMMIT();
#pragma unroll
        for (int m = 0; m < 2; m++)
#pragma unroll
            for (int n = 0; n < 2; n++)
#pragma unroll
                for (int q = 0; q < 4; q++) S[m][n][q] = 0.f;
        s_comp(smb + RINGO + s0 * SLOTB, 0);

        // ===== phase 1: S over d[128:256) from s1, softmax =====
        CP_WAIT1();
        __syncthreads();
        ld_v(s0, t, 1); CP_COMMIT();
        s_comp(smb + RINGO + s1 * SLOTB, 128);
        {
            const int r0 = lane >> 2;
            __half2* sp = (__half2*)(sm + PO);
            float* myL = sLb + wn * 64;
#pragma unroll
            for (int mt = 0; mt < 2; mt++) {
                const int rowa = wm * 32 + mt * 16 + r0;
                float sum0 = 0.f, sum1 = 0.f;
#pragma unroll
                for (int n = 0; n < 2; n++) {
                    const float* c = S[mt][n];
                    float e0 = __expf(c[0] * 0.0625f);
                    float e1 = __expf(c[1] * 0.0625f);
                    float e2 = __expf(c[2] * 0.0625f);
                    float e3 = __expf(c[3] * 0.0625f);
                    sum0 += e0 + e1; sum1 += e2 + e3;
                    const int col = wn * 16 + n * 8 + 2 * (lane & 3);
                    sp[(rowa * 72 + col) >> 1]       = __floats2half2_rn(e0, e1);
                    sp[((rowa + 8) * 72 + col) >> 1] = __floats2half2_rn(e2, e3);
                }
                sum0 += __shfl_xor_sync(0xffffffffu, sum0, 1);
                sum0 += __shfl_xor_sync(0xffffffffu, sum0, 2);
                sum1 += __shfl_xor_sync(0xffffffffu, sum1, 1);
                sum1 += __shfl_xor_sync(0xffffffffu, sum1, 2);
                if ((lane & 3) == 0) {
                    myL[rowa]     += sum0;
                    myL[rowa + 8] += sum1;
                }
            }
        }

        // ===== phase 2: merged PV (V0 @ s2, V1 @ s0); prefetch next K0 -> s1 =====
        CP_WAIT0();
        __syncthreads();
        if (t < NT - 1) ld_k(s1, t + 1, 0);
        CP_COMMIT();
        pv2(smb + RINGO + s2 * SLOTB, smb + RINGO + s0 * SLOTB);

        t3 = s1;
    }

    // ===== epilogue: O / l =====
    __syncthreads();
    const int r0 = lane >> 2;
#pragma unroll
    for (int mt = 0; mt < 2; mt++) {
        const int rowa = wm * 32 + mt * 16 + r0;
        const float l0 = sLb[rowa] + sLb[64 + rowa] + sLb[128 + rowa] + sLb[192 + rowa];
        const float l1 = sLb[rowa + 8] + sLb[64 + rowa + 8]
                       + sLb[128 + rowa + 8] + sLb[192 + rowa + 8];
        const float inv0 = 1.0f / l0;
        const float inv1 = 1.0f / l1;
        float* o0 = out + ((size_t)(b * SQL + q0 + rowa)) * DKL;
        float* o1 = o0 + 8 * DKL;
#pragma unroll
        for (int vc = 0; vc < 2; vc++)
#pragma unroll
            for (int n = 0; n < 4; n++) {
                const int col = vc * 128 + wn * 32 + (n >> 1) * 16 + (n & 1) * 8
                                + 2 * (lane & 3);
                const float* c = O[vc][mt][n];
                *(float2*)(o0 + col) = make_float2(c[0] * inv0, c[1] * inv0);
                *(float2*)(o1 + col) = make_float2(c[2] * inv1, c[3] * inv1);
            }
    }
}

// ---------------------------------------------------------------------------
// prep_a2: both conv inputs fp32 -> fp16, one launch.
// ---------------------------------------------------------------------------
__global__ void prep_a2(const float* __restrict__ A0, const float* __restrict__ A1,
                        __half* __restrict__ D0, __half* __restrict__ D1) {
    const int half_grid = gridDim.x >> 1;
    const float* A; __half* D; size_t blk;
    if (blockIdx.x < half_grid) { A = A0; D = D0; blk = blockIdx.x; }
    else                        { A = A1; D = D1; blk = blockIdx.x - half_grid; }
    const size_t i = (blk * 256 + threadIdx.x) * 8;
    float4 v0 = *(const float4*)(A + i);
    float4 v1 = *(const float4*)(A + i + 4);
    __half2 h[4];
    h[0] = __floats2half2_rn(v0.x, v0.y);
    h[1] = __floats2half2_rn(v0.z, v0.w);
    h[2] = __floats2half2_rn(v1.x, v1.y);
    h[3] = __floats2half2_rn(v1.z, v1.w);
    *(uint4*)(D + i) = *(uint4*)h;
}

// ---------------------------------------------------------------------------
// prep_w3: all three W[k][n] fp32 -> Wt fp16 [n][k] in one launch (grid.z=3).
// ---------------------------------------------------------------------------
__global__ void prep_w3(const float* __restrict__ W0, const float* __restrict__ W1,
                        const float* __restrict__ W2, __half* __restrict__ T) {
    __shared__ float tile[32][33];
    const float* W = (blockIdx.z == 0) ? W0 : (blockIdx.z == 1) ? W1 : W2;
    __half* Tz = T + (size_t)blockIdx.z * DINL * DKL;
    const int n0 = blockIdx.x * 32, k0 = blockIdx.y * 32;
    const int tx = threadIdx.x & 31, ty = threadIdx.x >> 5;
#pragma unroll
    for (int r = 0; r < 4; r++)
        tile[ty + 8 * r][tx] = W[(size_t)(k0 + ty + 8 * r) * DKL + n0 + tx];
    __syncthreads();
#pragma unroll
    for (int r = 0; r < 4; r++) {
        int n = ty + 8 * r;
        Tz[(size_t)(n0 + n) * DINL + k0 + tx] = __float2half_rn(tile[tx][n]);
    }
}

// ---------------------------------------------------------------------------
// Fused projection (unchanged — passing since R13): z=0 computes K+V, z=1 Q.
// ---------------------------------------------------------------------------
#define F_W0 0
#define F_W1 33792
#define F_A  67584
#define F_ASLOT 18432
#define SMEM_PROJ 104448

__global__ __launch_bounds__(256, 2) void proj_fused(
    const __half* __restrict__ Wt,
    const float* __restrict__ bk, const float* __restrict__ bv,
    const float* __restrict__ bq,
    __half* __restrict__ Kout, __half* __restrict__ Vout, __half* __restrict__ Qout) {
    extern __shared__ char sm[];
    const uint32_t smb = smem_u32(sm);
    const int tid = threadIdx.x;
    const int lane = tid & 31;
    const int w = tid >> 5;
    const int wm = w & 3, wn = w >> 2;
    const int m0 = blockIdx.x * 128;
    const int n0 = blockIdx.y * 64;
    const int z  = blockIdx.z;
    const bool kv = (z == 0);

    const __half* Ah = kv ? g_AL : g_AG;
    const __half* Wa = Wt + (size_t)(kv ? 0 : 2) * DINL * DKL;
    const __half* Wb = Wt + (size_t)1 * DINL * DKL;

    auto ld_a = [&](int slot, int kc) {
#pragma unroll
        for (int r = 0; r < 4; r++) {
            int idx = tid + r * 256;
            int row = idx >> 3, seg = idx & 7;
            cp16(smb + F_A + slot * F_ASLOT + (row * 72 + seg * 8) * 2,
                 Ah + (size_t)(m0 + row) * DINL + kc * 64 + seg * 8);
        }
    };

#pragma unroll
    for (int r = 0; r < 8; r++) {
        int idx = tid + r * 256;
        int row = idx >> 5, seg = idx & 31;
        cp16(smb + F_W0 + (row * 264 + seg * 8) * 2,
             Wa + (size_t)(n0 + row) * DINL + seg * 8);
        if (kv)
            cp16(smb + F_W1 + (row * 264 + seg * 8) * 2,
                 Wb + (size_t)(n0 + row) * DINL + seg * 8);
    }
    ld_a(0, 0); CP_COMMIT();
    ld_a(1, 1); CP_COMMIT();

    float accA[2][4][4], accB[2][4][4];
#pragma unroll
    for (int i = 0; i < 2; i++)
#pragma unroll
        for (int j = 0; j < 4; j++)
#pragma unroll
            for (int q = 0; q < 4; q++) { accA[i][j][q] = 0.f; accB[i][j][q] = 0.f; }

    for (int kc = 0; kc < 4; kc++) {
        if (kc == 3) { CP_WAIT0(); } else { CP_WAIT1(); }
        __syncthreads();
        const uint32_t abase = smb + F_A + (kc & 1) * F_ASLOT;
#pragma unroll
        for (int ks = 0; ks < 4; ks++) {
            const int k = ks * 16;
            uint32_t a[2][4], b0[2][4];
#pragma unroll
            for (int mt = 0; mt < 2; mt++)
                ldm4(a[mt], abase + ((wm * 32 + mt * 16 + (lane & 15)) * 72 + k
                                     + ((lane >> 4) * 8)) * 2);
#pragma unroll
            for (int nt2 = 0; nt2 < 2; nt2++)
                ldm4(b0[nt2], smb + F_W0 + ((wn * 32 + nt2 * 16 + (lane & 15)) * 264
                                            + kc * 64 + k + ((lane >> 4) * 8)) * 2);
#pragma unroll
            for (int mt = 0; mt < 2; mt++)
#pragma unroll
                for (int nt2 = 0; nt2 < 2; nt2++) {
                    mma16816(accA[mt][nt2 * 2 + 0], a[mt], b0[nt2][0], b0[nt2][2]);
                    mma16816(accA[mt][nt2 * 2 + 1], a[mt], b0[nt2][1], b0[nt2][3]);
                }
            if (kv) {
#pragma unroll
                for (int nt2 = 0; nt2 < 2; nt2++) {
                    uint32_t b1[4];
                    ldm4(b1, smb + F_W1 + ((wn * 32 + nt2 * 16 + (lane & 15)) * 264
                                           + kc * 64 + k + ((lane >> 4) * 8)) * 2);
#pragma unroll
                    for (int mt = 0; mt < 2; mt++) {
                        mma16816(accB[mt][nt2 * 2 + 0], a[mt], b1[0], b1[2]);
                        mma16816(accB[mt][nt2 * 2 + 1], a[mt], b1[1], b1[3]);
                    }
                }
            }
        }
        __syncthreads();
        if (kc < 2) ld_a(kc & 1, kc + 2);
        CP_COMMIT();
    }

    const float* biasA = kv ? bk : bq;
    __half* outA = kv ? Kout : Qout;
#pragma unroll
    for (int mt = 0; mt < 2; mt++)
#pragma unroll
        for (int nt = 0; nt < 4; nt++) {
            const int col = n0 + wn * 32 + (nt >> 1) * 16 + (nt & 1) * 8 + 2 * (lane & 3);
            const float b0 = biasA[col], b1 = biasA[col + 1];
            const int row = m0 + wm * 32 + mt * 16 + (lane >> 2);
            const float* c = accA[mt][nt];
            *(__half2*)(outA + (size_t)row * DKL + col) =
                __floats2half2_rn(c[0] + b0, c[1] + b1);
            *(__half2*)(outA + (size_t)(row + 8) * DKL + col) =
                __floats2half2_rn(c[2] + b0, c[3] + b1);
        }

    if (kv) {
        __syncthreads();
        __half* stage = (__half*)(sm + F_A);
#pragma unroll
        for (int mt = 0; mt < 2; mt++)
#pragma unroll
            for (int nt = 0; nt < 4; nt++) {
                const int cl = wn * 32 + (nt >> 1) * 16 + (nt & 1) * 8 + 2 * (lane & 3);
                const float b0 = bv[n0 + cl], b1 = bv[n0 + cl + 1];
                const int mr = wm * 32 + mt * 16 + (lane >> 2);
                const float* c = accB[mt][nt];
                stage[cl * 136 + mr]           = __float2half_rn(c[0] + b0);
                stage[(cl + 1) * 136 + mr]     = __float2half_rn(c[1] + b1);
                stage[cl * 136 + mr + 8]       = __float2half_rn(c[2] + b0);
                stage[(cl + 1) * 136 + mr + 8] = __float2half_rn(c[3] + b1);
            }
        __syncthreads();
        const int bb = m0 >> 12;
        const int skv0 = m0 & (SQL - 1);
#pragma unroll
        for (int r = 0; r < 4; r++) {
            int idx = tid + r * 256;
            int row = idx >> 4, seg = idx & 15;
            uint4 val = *(uint4*)&stage[row * 136 + seg * 8];
            *(uint4*)&Vout[(size_t)(bb * DKL + n0 + row) * SKVL + skv0 + seg * 8] = val;
        }
    }
}

// ---------------------------------------------------------------------------
extern "C" void kernel_launch(void* const* d_in, const int* in_sizes, int n_in,
                              void* d_out, int out_size) {
    (void)in_sizes; (void)n_in; (void)out_size;
    const float* conv_local  = (const float*)d_in[0];
    const float* conv_global = (const float*)d_in[1];
    const float* Wk = (const float*)d_in[2];
    const float* bk = (const float*)d_in[3];
    const float* Wq = (const float*)d_in[4];
    const float* bq = (const float*)d_in[5];
    const float* Wv = (const float*)d_in[6];
    const float* bv = (const float*)d_in[7];
    float* out = (float*)d_out;

    void *qh, *kh, *vt, *al, *ag, *wt;
    cudaGetSymbolAddress(&qh, g_Qh);
    cudaGetSymbolAddress(&kh, g_Kh);
    cudaGetSymbolAddress(&vt, g_Vt);
    cudaGetSymbolAddress(&al, g_AL);
    cudaGetSymbolAddress(&ag, g_AG);
    cudaGetSymbolAddress(&wt, g_Wt);

    const int nblk = (BB * SKVL * DINL) / (256 * 8);
    prep_a2<<<2 * nblk, 256>>>(conv_local, conv_global, (__half*)al, (__half*)ag);

    dim3 wgrid(8, 8, 3);
    prep_w3<<<wgrid, 256>>>(Wk, Wv, Wq, (__half*)wt);

    cudaFuncSetAttribute(proj_fused, cudaFuncAttributeMaxDynamicSharedMemorySize, SMEM_PROJ);
    dim3 ggrid((BB * SKVL) / 128, DKL / 64, 2);
    proj_fused<<<ggrid, 256, SMEM_PROJ>>>((const __half*)wt, bk, bv, bq,
                                          (__half*)kh, (__half*)vt, (__half*)qh);

    cudaFuncSetAttribute(attn_kernel, cudaFuncAttributeMaxDynamicSharedMemorySize, SMEM_ATTN);
    attn_kernel<<<BB * (SQL / 64), 256, SMEM_ATTN>>>(out);
}